// round 2
// baseline (speedup 1.0000x reference)
#include <cuda_runtime.h>
#include <cuda_bf16.h>
#include <math.h>

// Problem constants
#define BATCH 4
#define SEQ   2048
#define DIM   1024
#define HEADS 16
#define HDIM  64
#define MROWS (BATCH * SEQ)   // 8192

// Scratch (allocation-free rule: __device__ globals)
__device__ float g_Q[MROWS * DIM];
__device__ float g_K[MROWS * DIM];
__device__ float g_V[MROWS * DIM];
__device__ float g_C[MROWS * DIM];

// ---------------------------------------------------------------------------
// SGEMM: C[m,n] = sum_k A[m,k] * W[n,k] + bias[n]
// A: [M,K] row-major, W: [N,K] row-major (i.e. computes A @ W^T + b)
// 128x128 block tile, BK=8, 256 threads, 8x8 per thread.
// ---------------------------------------------------------------------------
#define BM 128
#define BN 128
#define BK 8
#define TM 8
#define TN 8

__global__ __launch_bounds__(256) void sgemm_nt_bias(
    const float* __restrict__ A, const float* __restrict__ W,
    const float* __restrict__ bias, float* __restrict__ C,
    int M, int N, int K)
{
    __shared__ float As[BK][BM];
    __shared__ float Bs[BK][BN];

    const int tid = threadIdx.x;
    const int bm = blockIdx.y * BM;
    const int bn = blockIdx.x * BN;

    // Load mapping: 128 rows x 8 k = 1024 floats -> 256 threads x 1 float4
    const int lrow = tid >> 1;          // 0..127
    const int lcol = (tid & 1) * 4;     // 0 or 4

    const float* Aptr = A + (size_t)(bm + lrow) * K + lcol;
    const float* Wptr = W + (size_t)(bn + lrow) * K + lcol;

    const int tr = (tid >> 4) * TM;     // 0..120
    const int tc = (tid & 15) * TN;     // 0..120

    float acc[TM][TN];
#pragma unroll
    for (int i = 0; i < TM; i++)
#pragma unroll
        for (int j = 0; j < TN; j++) acc[i][j] = 0.f;

    for (int k0 = 0; k0 < K; k0 += BK) {
        float4 a = *(const float4*)(Aptr + k0);
        float4 b = *(const float4*)(Wptr + k0);
        As[lcol + 0][lrow] = a.x;
        As[lcol + 1][lrow] = a.y;
        As[lcol + 2][lrow] = a.z;
        As[lcol + 3][lrow] = a.w;
        Bs[lcol + 0][lrow] = b.x;
        Bs[lcol + 1][lrow] = b.y;
        Bs[lcol + 2][lrow] = b.z;
        Bs[lcol + 3][lrow] = b.w;
        __syncthreads();

#pragma unroll
        for (int kk = 0; kk < BK; kk++) {
            float ar[TM], br[TN];
#pragma unroll
            for (int i = 0; i < TM; i++) ar[i] = As[kk][tr + i];
#pragma unroll
            for (int j = 0; j < TN; j++) br[j] = Bs[kk][tc + j];
#pragma unroll
            for (int i = 0; i < TM; i++)
#pragma unroll
                for (int j = 0; j < TN; j++)
                    acc[i][j] += ar[i] * br[j];
        }
        __syncthreads();
    }

#pragma unroll
    for (int i = 0; i < TM; i++) {
        float* crow = C + (size_t)(bm + tr + i) * N + bn + tc;
#pragma unroll
        for (int j = 0; j < TN; j += 4) {
            float4 v;
            v.x = acc[i][j + 0] + bias[bn + tc + j + 0];
            v.y = acc[i][j + 1] + bias[bn + tc + j + 1];
            v.z = acc[i][j + 2] + bias[bn + tc + j + 2];
            v.w = acc[i][j + 3] + bias[bn + tc + j + 3];
            *(float4*)(crow + j) = v;
        }
    }
}

// ---------------------------------------------------------------------------
// Flash attention (fp32, causal). One block = one (batch, head, 64-query tile).
// 256 threads = 64 query rows x 4 sub-lanes.
// QK: each sub-lane handles 16 keys (interleaved kk = 4j+sub for bank spread).
// PV: each sub-lane owns 16 output dims.
// ---------------------------------------------------------------------------
#define AQ 64
#define AK 64
#define SSTR (HDIM + 4)   // 68 floats per smem row

__global__ __launch_bounds__(256) void attn_kernel(
    const float* __restrict__ Q, const float* __restrict__ K,
    const float* __restrict__ V, float* __restrict__ O)
{
    extern __shared__ float sm[];
    float* Qs = sm;                        // 64*68
    float* Ks = Qs + AQ * SSTR;
    float* Vs = Ks + AK * SSTR;
    float* Ps = Vs + AK * SSTR;

    const int tid = threadIdx.x;
    const int tq  = tid >> 2;     // query row 0..63
    const int sub = tid & 3;      // 0..3
    const int qtile = blockIdx.x;
    const int h     = blockIdx.y;
    const int b     = blockIdx.z;
    const int q0 = qtile * AQ;

    const size_t base = (size_t)b * SEQ * DIM + (size_t)h * HDIM;

    // Load Q tile into smem
    {
        const int r  = tid >> 2;
        const int c0 = (tid & 3) * 16;
        const float* src = Q + base + (size_t)(q0 + r) * DIM + c0;
        float* dst = Qs + r * SSTR + c0;
#pragma unroll
        for (int i = 0; i < 16; i += 4)
            *(float4*)(dst + i) = *(const float4*)(src + i);
    }

    float m_run = -INFINITY;
    float l_run = 0.f;
    float out[16];
#pragma unroll
    for (int i = 0; i < 16; i++) out[i] = 0.f;
    const int dc = sub * 16;   // dim offset this thread owns for PV

    for (int kt = 0; kt <= qtile; kt++) {
        __syncthreads();   // previous iter's Ps/Vs reads done; also orders Qs (iter 0)
        const int k0 = kt * AK;
        {
            const int r  = tid >> 2;
            const int c0 = (tid & 3) * 16;
            const float* ksrc = K + base + (size_t)(k0 + r) * DIM + c0;
            const float* vsrc = V + base + (size_t)(k0 + r) * DIM + c0;
            float* kd = Ks + r * SSTR + c0;
            float* vd = Vs + r * SSTR + c0;
#pragma unroll
            for (int i = 0; i < 16; i += 4) {
                *(float4*)(kd + i) = *(const float4*)(ksrc + i);
                *(float4*)(vd + i) = *(const float4*)(vsrc + i);
            }
        }
        __syncthreads();

        // --- scores: this thread handles keys kk = 4j + sub ---
        const bool full = (kt < qtile);
        float sc[16];
        float rowmax = -INFINITY;
        const float* qrow = Qs + tq * SSTR;
#pragma unroll
        for (int j = 0; j < 16; j++) {
            const int kk = j * 4 + sub;
            const float* krow = Ks + kk * SSTR;
            float d0 = 0.f, d1 = 0.f, d2 = 0.f, d3 = 0.f;
#pragma unroll
            for (int d = 0; d < HDIM; d += 4) {
                d0 += qrow[d + 0] * krow[d + 0];
                d1 += qrow[d + 1] * krow[d + 1];
                d2 += qrow[d + 2] * krow[d + 2];
                d3 += qrow[d + 3] * krow[d + 3];
            }
            float s = ((d0 + d1) + (d2 + d3)) * 0.125f;  // 1/sqrt(64)
            if (!full && (k0 + kk > q0 + tq)) s = -INFINITY;
            sc[j] = s;
            rowmax = fmaxf(rowmax, s);
        }
        rowmax = fmaxf(rowmax, __shfl_xor_sync(0xffffffffu, rowmax, 1));
        rowmax = fmaxf(rowmax, __shfl_xor_sync(0xffffffffu, rowmax, 2));

        const float mnew = fmaxf(m_run, rowmax);
        const float corr = __expf(m_run - mnew);   // -inf -> 0 on first tile
        float lsum = 0.f;
#pragma unroll
        for (int j = 0; j < 16; j++) {
            float p = __expf(sc[j] - mnew);
            lsum += p;
            Ps[tq * SSTR + j * 4 + sub] = p;
        }
        lsum += __shfl_xor_sync(0xffffffffu, lsum, 1);
        lsum += __shfl_xor_sync(0xffffffffu, lsum, 2);
        l_run = l_run * corr + lsum;
        m_run = mnew;
#pragma unroll
        for (int i = 0; i < 16; i++) out[i] *= corr;

        __syncthreads();   // Ps visible to whole quad / block

        // --- PV: out[dc..dc+15] += P[tq][k] * V[k][dc..dc+15] ---
        const float* prow = Ps + tq * SSTR;
#pragma unroll 4
        for (int k = 0; k < AK; k++) {
            const float p = prow[k];
            const float* vrow = Vs + k * SSTR + dc;
#pragma unroll
            for (int i = 0; i < 16; i++) out[i] += p * vrow[i];
        }
    }

    const float inv = 1.f / l_run;
    float* dst = O + base + (size_t)(q0 + tq) * DIM + dc;
#pragma unroll
    for (int i = 0; i < 16; i += 4) {
        float4 v;
        v.x = out[i + 0] * inv;
        v.y = out[i + 1] * inv;
        v.z = out[i + 2] * inv;
        v.w = out[i + 3] * inv;
        *(float4*)(dst + i) = v;
    }
}

// ---------------------------------------------------------------------------
// Launch
// ---------------------------------------------------------------------------
extern "C" void kernel_launch(void* const* d_in, const int* in_sizes, int n_in,
                              void* d_out, int out_size)
{
    const float* q  = (const float*)d_in[0];
    // d_in[1] = mask (all-true by construction; padding mask is a no-op)
    const float* Wq = (const float*)d_in[2];
    const float* bq = (const float*)d_in[3];
    const float* Wk = (const float*)d_in[4];
    const float* bk = (const float*)d_in[5];
    const float* Wv = (const float*)d_in[6];
    const float* bv = (const float*)d_in[7];
    const float* Wo = (const float*)d_in[8];
    const float* bo = (const float*)d_in[9];
    float* out = (float*)d_out;

    float *Qb, *Kb, *Vb, *Cb;
    cudaGetSymbolAddress((void**)&Qb, g_Q);
    cudaGetSymbolAddress((void**)&Kb, g_K);
    cudaGetSymbolAddress((void**)&Vb, g_V);
    cudaGetSymbolAddress((void**)&Cb, g_C);

    const dim3 gemmGrid(DIM / BN, MROWS / BM);   // (8, 64)
    sgemm_nt_bias<<<gemmGrid, 256>>>(q, Wq, bq, Qb, MROWS, DIM, DIM);
    sgemm_nt_bias<<<gemmGrid, 256>>>(q, Wk, bk, Kb, MROWS, DIM, DIM);
    sgemm_nt_bias<<<gemmGrid, 256>>>(q, Wv, bv, Vb, MROWS, DIM, DIM);

    const int smem = 4 * AQ * SSTR * sizeof(float);   // 69632 B
    static int attr_set = 0;
    cudaFuncSetAttribute(attn_kernel, cudaFuncAttributeMaxDynamicSharedMemorySize, smem);
    (void)attr_set;
    const dim3 attnGrid(SEQ / AQ, HEADS, BATCH);      // (32, 16, 4)
    attn_kernel<<<attnGrid, 256, smem>>>(Qb, Kb, Vb, Cb);

    sgemm_nt_bias<<<gemmGrid, 256>>>(Cb, Wo, bo, out, MROWS, DIM, DIM);
}

// round 5
// speedup vs baseline: 2.6795x; 2.6795x over previous
#include <cuda_runtime.h>
#include <cuda_bf16.h>
#include <cstdint>
#include <math.h>

// ---------------- problem constants ----------------
#define BATCH 4
#define SEQ   2048
#define DIM   1024
#define HEADS 16
#define HDIM  64
#define MROWS (BATCH * SEQ)   // 8192

// ---------------- scratch (device globals; no allocs allowed) ----------------
__device__ float g_Q[MROWS * DIM];
__device__ float g_K[MROWS * DIM];
__device__ float g_V[MROWS * DIM];
__device__ float g_C[MROWS * DIM];
__device__ __nv_bfloat16 g_xhi[MROWS * DIM];   // activation split (q, later C)
__device__ __nv_bfloat16 g_xlo[MROWS * DIM];
__device__ __nv_bfloat16 g_whi[4][DIM * DIM];  // Wq,Wk,Wv,Wo splits
__device__ __nv_bfloat16 g_wlo[4][DIM * DIM];

// ---------------- small helpers ----------------
__device__ __forceinline__ uint32_t smem_to_u32(const void* p) {
    uint32_t a;
    asm("{ .reg .u64 t; cvta.to.shared.u64 t, %1; cvt.u32.u64 %0, t; }" : "=r"(a) : "l"(p));
    return a;
}
__device__ __forceinline__ void ldsm4(uint32_t* r, uint32_t addr) {
    asm volatile("ldmatrix.sync.aligned.m8n8.x4.shared.b16 {%0,%1,%2,%3}, [%4];"
                 : "=r"(r[0]), "=r"(r[1]), "=r"(r[2]), "=r"(r[3]) : "r"(addr));
}
__device__ __forceinline__ void mma_bf16(float* c, const uint32_t* a, uint32_t b0, uint32_t b1) {
    asm volatile("mma.sync.aligned.m16n8k16.row.col.f32.bf16.bf16.f32 "
                 "{%0,%1,%2,%3}, {%4,%5,%6,%7}, {%8,%9}, {%0,%1,%2,%3};"
                 : "+f"(c[0]), "+f"(c[1]), "+f"(c[2]), "+f"(c[3])
                 : "r"(a[0]), "r"(a[1]), "r"(a[2]), "r"(a[3]), "r"(b0), "r"(b1));
}
#define CP_ASYNC16(dst, src) \
    asm volatile("cp.async.cg.shared.global [%0], [%1], 16;" :: "r"(dst), "l"(src) : "memory")
#define CP_COMMIT() asm volatile("cp.async.commit_group;" ::: "memory")
#define CP_WAIT(n)  asm volatile("cp.async.wait_group %0;" :: "n"(n) : "memory")

// ---------------- split fp32 -> bf16 hi/lo ----------------
__global__ __launch_bounds__(256) void split_kernel(
    const float* __restrict__ x, __nv_bfloat16* __restrict__ hi,
    __nv_bfloat16* __restrict__ lo, int n4)
{
    int i = blockIdx.x * blockDim.x + threadIdx.x;
    if (i >= n4) return;
    float4 v = ((const float4*)x)[i];
    __nv_bfloat16 h0 = __float2bfloat16(v.x), h1 = __float2bfloat16(v.y);
    __nv_bfloat16 h2 = __float2bfloat16(v.z), h3 = __float2bfloat16(v.w);
    __nv_bfloat16 l0 = __float2bfloat16(v.x - __bfloat162float(h0));
    __nv_bfloat16 l1 = __float2bfloat16(v.y - __bfloat162float(h1));
    __nv_bfloat16 l2 = __float2bfloat16(v.z - __bfloat162float(h2));
    __nv_bfloat16 l3 = __float2bfloat16(v.w - __bfloat162float(h3));
    __nv_bfloat162* H = (__nv_bfloat162*)hi;
    __nv_bfloat162* L = (__nv_bfloat162*)lo;
    H[2 * i]     = __nv_bfloat162(h0, h1);
    H[2 * i + 1] = __nv_bfloat162(h2, h3);
    L[2 * i]     = __nv_bfloat162(l0, l1);
    L[2 * i + 1] = __nv_bfloat162(l2, l3);
}

// ---------------- HMMA bf16-split GEMM: C = A @ W^T + bias ----------------
// A: [8192,1024], W: [1024,1024] row-major (K contiguous).
// Block tile 128x128, K-chunk 32, double-buffered cp.async.
// 8 warps, each 64x32 (m16n8k16 atoms: 4 x 4).
#define KC 32
#define NS (DIM / KC)            // 32 stages
#define PSB 80                   // padded row stride in bytes (32 bf16 + 8 pad)
#define MAT (128 * PSB)          // 10240 B per matrix tile
#define STAGE (4 * MAT)          // Ahi, Alo, Bhi, Blo
#define GEMM_SMEM (2 * STAGE)    // 81920 B

__global__ __launch_bounds__(256, 1) void gemm_tc(
    const __nv_bfloat16* __restrict__ Ahi, const __nv_bfloat16* __restrict__ Alo,
    const __nv_bfloat16* __restrict__ Bhi, const __nv_bfloat16* __restrict__ Blo,
    const float* __restrict__ bias, float* __restrict__ C)
{
    extern __shared__ char smem[];
    const uint32_t sbase = smem_to_u32(smem);
    const int tid  = threadIdx.x;
    const int wid  = tid >> 5;
    const int lane = tid & 31;
    const int gm0 = blockIdx.y * 128;
    const int gn0 = blockIdx.x * 128;
    const int wm = (wid >> 2) * 64;   // 0 or 64
    const int wn = (wid & 3) * 32;    // 0,32,64,96

    const __nv_bfloat16* srcA[2] = {Ahi, Alo};
    const __nv_bfloat16* srcB[2] = {Bhi, Blo};

    float acc[4][4][4];
#pragma unroll
    for (int i = 0; i < 4; i++)
#pragma unroll
        for (int j = 0; j < 4; j++)
#pragma unroll
            for (int f = 0; f < 4; f++) acc[i][j][f] = 0.f;

    auto load_stage = [&](int ks, int buf) {
#pragma unroll
        for (int i = 0; i < 8; i++) {
            const int m   = i >> 1;                 // 0:Ahi 1:Alo 2:Bhi 3:Blo
            const int idx = ((i & 1) << 8) | tid;   // 0..511
            const int r   = idx >> 2;               // 0..127
            const int c   = idx & 3;                // 16B unit
            const __nv_bfloat16* src = (m < 2)
                ? srcA[m]     + (size_t)(gm0 + r) * DIM + ks * KC + c * 8
                : srcB[m - 2] + (size_t)(gn0 + r) * DIM + ks * KC + c * 8;
            const uint32_t dst = sbase + buf * STAGE + m * MAT + r * PSB + c * 16;
            CP_ASYNC16(dst, src);
        }
    };

    const int aRow = lane & 15;                              // + wm + 16*i
    const int aCol = (lane >> 4) * 16;                       // + s*32
    const int bRow = ((lane >> 4) & 1) * 8 + (lane & 7);     // + wn + 16*p
    const int bCol = ((lane >> 3) & 1) * 16;                 // + s*32

    auto compute_stage = [&](int buf) {
        const uint32_t sb = sbase + buf * STAGE;
#pragma unroll
        for (int s = 0; s < 2; s++) {
            uint32_t la[16], lal[16], lbh[8], lbl[8];
            const int kb = s * 32;
#pragma unroll
            for (int i = 0; i < 4; i++)
                ldsm4(la + 4 * i, sb + 0 * MAT + (wm + 16 * i + aRow) * PSB + kb + aCol);
#pragma unroll
            for (int p = 0; p < 2; p++)
                ldsm4(lbh + 4 * p, sb + 2 * MAT + (wn + 16 * p + bRow) * PSB + kb + bCol);
#pragma unroll
            for (int i = 0; i < 4; i++)
#pragma unroll
                for (int j = 0; j < 4; j++)
                    mma_bf16(acc[i][j], la + 4 * i,
                             lbh[(j >> 1) * 4 + (j & 1) * 2], lbh[(j >> 1) * 4 + (j & 1) * 2 + 1]);
#pragma unroll
            for (int p = 0; p < 2; p++)
                ldsm4(lbl + 4 * p, sb + 3 * MAT + (wn + 16 * p + bRow) * PSB + kb + bCol);
#pragma unroll
            for (int i = 0; i < 4; i++)
#pragma unroll
                for (int j = 0; j < 4; j++)
                    mma_bf16(acc[i][j], la + 4 * i,
                             lbl[(j >> 1) * 4 + (j & 1) * 2], lbl[(j >> 1) * 4 + (j & 1) * 2 + 1]);
#pragma unroll
            for (int i = 0; i < 4; i++)
                ldsm4(lal + 4 * i, sb + 1 * MAT + (wm + 16 * i + aRow) * PSB + kb + aCol);
#pragma unroll
            for (int i = 0; i < 4; i++)
#pragma unroll
                for (int j = 0; j < 4; j++)
                    mma_bf16(acc[i][j], lal + 4 * i,
                             lbh[(j >> 1) * 4 + (j & 1) * 2], lbh[(j >> 1) * 4 + (j & 1) * 2 + 1]);
        }
    };

    load_stage(0, 0);
    CP_COMMIT();
    for (int ks = 0; ks < NS; ks++) {
        const int buf = ks & 1;
        if (ks + 1 < NS) {
            load_stage(ks + 1, buf ^ 1);
            CP_COMMIT();
            CP_WAIT(1);
        } else {
            CP_WAIT(0);
        }
        __syncthreads();
        compute_stage(buf);
        __syncthreads();
    }

    // epilogue: direct stores with bias
#pragma unroll
    for (int i = 0; i < 4; i++) {
        const int r0 = gm0 + wm + 16 * i + (lane >> 2);
        const int r1 = r0 + 8;
#pragma unroll
        for (int j = 0; j < 4; j++) {
            const int col = gn0 + wn + 8 * j + 2 * (lane & 3);
            const float b0 = __ldg(&bias[col]);
            const float b1 = __ldg(&bias[col + 1]);
            float2 v0 = make_float2(acc[i][j][0] + b0, acc[i][j][1] + b1);
            float2 v1 = make_float2(acc[i][j][2] + b0, acc[i][j][3] + b1);
            *(float2*)(C + (size_t)r0 * DIM + col) = v0;
            *(float2*)(C + (size_t)r1 * DIM + col) = v1;
        }
    }
}

// ---------------- fast 2^t on the FMA pipe ----------------
__device__ __forceinline__ float fexp2(float t) {
    t = fmaxf(t, -126.f);
    float z = t + 12582912.f;               // 1.5*2^23: round-to-nearest integer
    int   n = __float_as_int(z);
    float f = t - (z - 12582912.f);         // f in [-0.5, 0.5]
    float p = 1.33335581e-3f;
    p = fmaf(p, f, 9.61812911e-3f);
    p = fmaf(p, f, 5.55041087e-2f);
    p = fmaf(p, f, 2.40226507e-1f);
    p = fmaf(p, f, 6.93147182e-1f);
    p = fmaf(p, f, 1.0f);
    return __int_as_float(__float_as_int(p) + (n << 23));
}
#define LOG2E 1.4426950408889634f

// ---------------- flash attention, 4x4 register tiles ----------------
#define AQ 64
#define AK 64
#define ASTR 68

__global__ __launch_bounds__(256) void attn_kernel(
    const float* __restrict__ Q, const float* __restrict__ K,
    const float* __restrict__ V, float* __restrict__ O)
{
    extern __shared__ float sm[];
    float* Qs = sm;                     // 64 x 68
    float* Ks = Qs + AQ * ASTR;
    float* Vs = Ks + AK * ASTR;
    float* Ps = Vs + AK * ASTR;

    const int tid = threadIdx.x;
    const int qg = tid >> 4;            // 0..15: owns q rows qg*4..+3
    const int sg = tid & 15;            // kg in QK, dg in PV
    const int qtile = blockIdx.x, h = blockIdx.y, b = blockIdx.z;
    const int q0 = qtile * AQ;
    const size_t base = (size_t)b * SEQ * DIM + (size_t)h * HDIM;

    {
        const int r = tid >> 2, c0 = (tid & 3) * 16;
        const float* src = Q + base + (size_t)(q0 + r) * DIM + c0;
        float* dst = Qs + r * ASTR + c0;
#pragma unroll
        for (int i = 0; i < 16; i += 4) {
            float4 v = *(const float4*)(src + i);
            v.x *= 0.125f; v.y *= 0.125f; v.z *= 0.125f; v.w *= 0.125f;
            *(float4*)(dst + i) = v;
        }
    }

    float m_run[4], l_run[4], out[4][4];
#pragma unroll
    for (int i = 0; i < 4; i++) {
        m_run[i] = -1e30f; l_run[i] = 0.f;
#pragma unroll
        for (int j = 0; j < 4; j++) out[i][j] = 0.f;
    }

    for (int kt = 0; kt <= qtile; kt++) {
        const int k0 = kt * AK;
        __syncthreads();
        {
            const int r = tid >> 2, c0 = (tid & 3) * 16;
            const float* ksrc = K + base + (size_t)(k0 + r) * DIM + c0;
            const float* vsrc = V + base + (size_t)(k0 + r) * DIM + c0;
            float* kd = Ks + r * ASTR + c0;
            float* vd = Vs + r * ASTR + c0;
#pragma unroll
            for (int i = 0; i < 16; i += 4) {
                *(float4*)(kd + i) = *(const float4*)(ksrc + i);
                *(float4*)(vd + i) = *(const float4*)(vsrc + i);
            }
        }
        __syncthreads();

        float s[4][4];
#pragma unroll
        for (int i = 0; i < 4; i++)
#pragma unroll
            for (int j = 0; j < 4; j++) s[i][j] = 0.f;

#pragma unroll 4
        for (int d0 = 0; d0 < HDIM; d0 += 4) {
            float4 q4[4], k4[4];
#pragma unroll
            for (int i = 0; i < 4; i++) q4[i] = *(const float4*)(Qs + (qg * 4 + i) * ASTR + d0);
#pragma unroll
            for (int j = 0; j < 4; j++) k4[j] = *(const float4*)(Ks + (sg + 16 * j) * ASTR + d0);
#pragma unroll
            for (int i = 0; i < 4; i++)
#pragma unroll
                for (int j = 0; j < 4; j++) {
                    s[i][j] = fmaf(q4[i].x, k4[j].x, s[i][j]);
                    s[i][j] = fmaf(q4[i].y, k4[j].y, s[i][j]);
                    s[i][j] = fmaf(q4[i].z, k4[j].z, s[i][j]);
                    s[i][j] = fmaf(q4[i].w, k4[j].w, s[i][j]);
                }
        }
        if (kt == qtile) {
#pragma unroll
            for (int i = 0; i < 4; i++)
#pragma unroll
                for (int j = 0; j < 4; j++)
                    if (sg + 16 * j > qg * 4 + i) s[i][j] = -1e30f;
        }

#pragma unroll
        for (int i = 0; i < 4; i++) {
            float rm = fmaxf(fmaxf(s[i][0], s[i][1]), fmaxf(s[i][2], s[i][3]));
            rm = fmaxf(rm, __shfl_xor_sync(0xffffffffu, rm, 1));
            rm = fmaxf(rm, __shfl_xor_sync(0xffffffffu, rm, 2));
            rm = fmaxf(rm, __shfl_xor_sync(0xffffffffu, rm, 4));
            rm = fmaxf(rm, __shfl_xor_sync(0xffffffffu, rm, 8));
            const float mnew = fmaxf(m_run[i], rm);
            const float corr = fexp2((m_run[i] - mnew) * LOG2E);
            float ls = 0.f;
#pragma unroll
            for (int j = 0; j < 4; j++) {
                float p = fexp2((s[i][j] - mnew) * LOG2E);
                ls += p;
                Ps[(qg * 4 + i) * ASTR + sg + 16 * j] = p;
            }
            ls += __shfl_xor_sync(0xffffffffu, ls, 1);
            ls += __shfl_xor_sync(0xffffffffu, ls, 2);
            ls += __shfl_xor_sync(0xffffffffu, ls, 4);
            ls += __shfl_xor_sync(0xffffffffu, ls, 8);
            l_run[i] = l_run[i] * corr + ls;
            m_run[i] = mnew;
#pragma unroll
            for (int j = 0; j < 4; j++) out[i][j] *= corr;
        }
        __syncthreads();

#pragma unroll 4
        for (int k = 0; k < AK; k++) {
            float p0 = Ps[(qg * 4 + 0) * ASTR + k];
            float p1 = Ps[(qg * 4 + 1) * ASTR + k];
            float p2 = Ps[(qg * 4 + 2) * ASTR + k];
            float p3 = Ps[(qg * 4 + 3) * ASTR + k];
            const float* vr = Vs + k * ASTR + sg;
#pragma unroll
            for (int l = 0; l < 4; l++) {
                const float v = vr[16 * l];
                out[0][l] = fmaf(p0, v, out[0][l]);
                out[1][l] = fmaf(p1, v, out[1][l]);
                out[2][l] = fmaf(p2, v, out[2][l]);
                out[3][l] = fmaf(p3, v, out[3][l]);
            }
        }
    }

#pragma unroll
    for (int i = 0; i < 4; i++) {
        const float inv = 1.f / l_run[i];
        float* dst = O + base + (size_t)(q0 + qg * 4 + i) * DIM + sg;
#pragma unroll
        for (int l = 0; l < 4; l++) dst[16 * l] = out[i][l] * inv;
    }
}

// ---------------- launch ----------------
extern "C" void kernel_launch(void* const* d_in, const int* in_sizes, int n_in,
                              void* d_out, int out_size)
{
    const float* q  = (const float*)d_in[0];
    const float* Wq = (const float*)d_in[2];
    const float* bq = (const float*)d_in[3];
    const float* Wk = (const float*)d_in[4];
    const float* bk = (const float*)d_in[5];
    const float* Wv = (const float*)d_in[6];
    const float* bv = (const float*)d_in[7];
    const float* Wo = (const float*)d_in[8];
    const float* bo = (const float*)d_in[9];
    float* out = (float*)d_out;

    float *Qb, *Kb, *Vb, *Cb;
    __nv_bfloat16 *xhi, *xlo, *whi, *wlo;
    cudaGetSymbolAddress((void**)&Qb, g_Q);
    cudaGetSymbolAddress((void**)&Kb, g_K);
    cudaGetSymbolAddress((void**)&Vb, g_V);
    cudaGetSymbolAddress((void**)&Cb, g_C);
    cudaGetSymbolAddress((void**)&xhi, g_xhi);
    cudaGetSymbolAddress((void**)&xlo, g_xlo);
    cudaGetSymbolAddress((void**)&whi, g_whi);
    cudaGetSymbolAddress((void**)&wlo, g_wlo);

    cudaFuncSetAttribute(gemm_tc, cudaFuncAttributeMaxDynamicSharedMemorySize, GEMM_SMEM);
    const int attn_smem = 4 * AQ * ASTR * sizeof(float);   // 69632
    cudaFuncSetAttribute(attn_kernel, cudaFuncAttributeMaxDynamicSharedMemorySize, attn_smem);

    const int nX4 = MROWS * DIM / 4;
    const int nW4 = DIM * DIM / 4;

    split_kernel<<<nX4 / 256, 256>>>(q, xhi, xlo, nX4);
    split_kernel<<<nW4 / 256, 256>>>(Wq, whi + 0 * (size_t)DIM * DIM, wlo + 0 * (size_t)DIM * DIM, nW4);
    split_kernel<<<nW4 / 256, 256>>>(Wk, whi + 1 * (size_t)DIM * DIM, wlo + 1 * (size_t)DIM * DIM, nW4);
    split_kernel<<<nW4 / 256, 256>>>(Wv, whi + 2 * (size_t)DIM * DIM, wlo + 2 * (size_t)DIM * DIM, nW4);
    split_kernel<<<nW4 / 256, 256>>>(Wo, whi + 3 * (size_t)DIM * DIM, wlo + 3 * (size_t)DIM * DIM, nW4);

    const dim3 ggrid(DIM / 128, MROWS / 128);   // (8, 64)
    gemm_tc<<<ggrid, 256, GEMM_SMEM>>>(xhi, xlo, whi + 0 * (size_t)DIM * DIM, wlo + 0 * (size_t)DIM * DIM, bq, Qb);
    gemm_tc<<<ggrid, 256, GEMM_SMEM>>>(xhi, xlo, whi + 1 * (size_t)DIM * DIM, wlo + 1 * (size_t)DIM * DIM, bk, Kb);
    gemm_tc<<<ggrid, 256, GEMM_SMEM>>>(xhi, xlo, whi + 2 * (size_t)DIM * DIM, wlo + 2 * (size_t)DIM * DIM, bv, Vb);

    const dim3 agrid(SEQ / AQ, HEADS, BATCH);   // (32, 16, 4)
    attn_kernel<<<agrid, 256, attn_smem>>>(Qb, Kb, Vb, Cb);

    split_kernel<<<nX4 / 256, 256>>>(Cb, xhi, xlo, nX4);
    gemm_tc<<<ggrid, 256, GEMM_SMEM>>>(xhi, xlo, whi + 3 * (size_t)DIM * DIM, wlo + 3 * (size_t)DIM * DIM, bo, out);
}

// round 6
// speedup vs baseline: 3.6755x; 1.3717x over previous
#include <cuda_runtime.h>
#include <cuda_bf16.h>
#include <cuda_fp16.h>
#include <cstdint>
#include <math.h>

// ---------------- problem constants ----------------
#define BATCH 4
#define SEQ   2048
#define DIM   1024
#define HEADS 16
#define HDIM  64
#define MROWS (BATCH * SEQ)   // 8192

// ---------------- scratch (device globals; no allocs allowed) ----------------
__device__ float g_C[MROWS * DIM];                 // attention output (fp32)
__device__ __half g_Qh[MROWS * DIM];               // projected Q/K/V in fp16
__device__ __half g_Kh[MROWS * DIM];
__device__ __half g_Vh[MROWS * DIM];
__device__ __nv_bfloat16 g_xhi[MROWS * DIM];       // activation split
__device__ __nv_bfloat16 g_xlo[MROWS * DIM];
__device__ __nv_bfloat16 g_whi[4][DIM * DIM];      // Wq,Wk,Wv,Wo splits
__device__ __nv_bfloat16 g_wlo[4][DIM * DIM];

// ---------------- small helpers ----------------
__device__ __forceinline__ uint32_t smem_to_u32(const void* p) {
    uint32_t a;
    asm("{ .reg .u64 t; cvta.to.shared.u64 t, %1; cvt.u32.u64 %0, t; }" : "=r"(a) : "l"(p));
    return a;
}
__device__ __forceinline__ void ldsm4(uint32_t* r, uint32_t addr) {
    asm volatile("ldmatrix.sync.aligned.m8n8.x4.shared.b16 {%0,%1,%2,%3}, [%4];"
                 : "=r"(r[0]), "=r"(r[1]), "=r"(r[2]), "=r"(r[3]) : "r"(addr));
}
__device__ __forceinline__ void ldsm4t(uint32_t* r, uint32_t addr) {
    asm volatile("ldmatrix.sync.aligned.m8n8.x4.trans.shared.b16 {%0,%1,%2,%3}, [%4];"
                 : "=r"(r[0]), "=r"(r[1]), "=r"(r[2]), "=r"(r[3]) : "r"(addr));
}
__device__ __forceinline__ void mma_bf16(float* c, const uint32_t* a, uint32_t b0, uint32_t b1) {
    asm volatile("mma.sync.aligned.m16n8k16.row.col.f32.bf16.bf16.f32 "
                 "{%0,%1,%2,%3}, {%4,%5,%6,%7}, {%8,%9}, {%0,%1,%2,%3};"
                 : "+f"(c[0]), "+f"(c[1]), "+f"(c[2]), "+f"(c[3])
                 : "r"(a[0]), "r"(a[1]), "r"(a[2]), "r"(a[3]), "r"(b0), "r"(b1));
}
__device__ __forceinline__ void mma_f16(float* c, const uint32_t* a, uint32_t b0, uint32_t b1) {
    asm volatile("mma.sync.aligned.m16n8k16.row.col.f32.f16.f16.f32 "
                 "{%0,%1,%2,%3}, {%4,%5,%6,%7}, {%8,%9}, {%0,%1,%2,%3};"
                 : "+f"(c[0]), "+f"(c[1]), "+f"(c[2]), "+f"(c[3])
                 : "r"(a[0]), "r"(a[1]), "r"(a[2]), "r"(a[3]), "r"(b0), "r"(b1));
}
__device__ __forceinline__ uint32_t packh2(float a, float b) {
    __half2 h = __floats2half2_rn(a, b);
    return *reinterpret_cast<uint32_t*>(&h);
}
#define CP_ASYNC16(dst, src) \
    asm volatile("cp.async.cg.shared.global [%0], [%1], 16;" :: "r"(dst), "l"(src) : "memory")
#define CP_COMMIT() asm volatile("cp.async.commit_group;" ::: "memory")
#define CP_WAIT(n)  asm volatile("cp.async.wait_group %0;" :: "n"(n) : "memory")

// ---------------- split fp32 -> bf16 hi/lo ----------------
__global__ __launch_bounds__(256) void split_kernel(
    const float* __restrict__ x, __nv_bfloat16* __restrict__ hi,
    __nv_bfloat16* __restrict__ lo, int n4)
{
    int i = blockIdx.x * blockDim.x + threadIdx.x;
    if (i >= n4) return;
    float4 v = ((const float4*)x)[i];
    __nv_bfloat16 h0 = __float2bfloat16(v.x), h1 = __float2bfloat16(v.y);
    __nv_bfloat16 h2 = __float2bfloat16(v.z), h3 = __float2bfloat16(v.w);
    __nv_bfloat16 l0 = __float2bfloat16(v.x - __bfloat162float(h0));
    __nv_bfloat16 l1 = __float2bfloat16(v.y - __bfloat162float(h1));
    __nv_bfloat16 l2 = __float2bfloat16(v.z - __bfloat162float(h2));
    __nv_bfloat16 l3 = __float2bfloat16(v.w - __bfloat162float(h3));
    __nv_bfloat162* H = (__nv_bfloat162*)hi;
    __nv_bfloat162* L = (__nv_bfloat162*)lo;
    H[2 * i]     = __nv_bfloat162(h0, h1);
    H[2 * i + 1] = __nv_bfloat162(h2, h3);
    L[2 * i]     = __nv_bfloat162(l0, l1);
    L[2 * i + 1] = __nv_bfloat162(l2, l3);
}

// ---------------- HMMA bf16-split GEMM: C = A @ W^T + bias ----------------
#define KC 32
#define NS (DIM / KC)            // 32 stages
#define PSB 80                   // padded row stride in bytes
#define MAT (128 * PSB)
#define STAGE (4 * MAT)
#define GEMM_SMEM (2 * STAGE)    // 81920 B

template <typename OutT>
__global__ __launch_bounds__(256, 1) void gemm_tc(
    const __nv_bfloat16* __restrict__ Ahi, const __nv_bfloat16* __restrict__ Alo,
    const __nv_bfloat16* __restrict__ Bhi, const __nv_bfloat16* __restrict__ Blo,
    const float* __restrict__ bias, OutT* __restrict__ C)
{
    extern __shared__ char smem[];
    const uint32_t sbase = smem_to_u32(smem);
    const int tid  = threadIdx.x;
    const int wid  = tid >> 5;
    const int lane = tid & 31;
    const int gm0 = blockIdx.y * 128;
    const int gn0 = blockIdx.x * 128;
    const int wm = (wid >> 2) * 64;
    const int wn = (wid & 3) * 32;

    const __nv_bfloat16* srcA[2] = {Ahi, Alo};
    const __nv_bfloat16* srcB[2] = {Bhi, Blo};

    float acc[4][4][4];
#pragma unroll
    for (int i = 0; i < 4; i++)
#pragma unroll
        for (int j = 0; j < 4; j++)
#pragma unroll
            for (int f = 0; f < 4; f++) acc[i][j][f] = 0.f;

    auto load_stage = [&](int ks, int buf) {
#pragma unroll
        for (int i = 0; i < 8; i++) {
            const int m   = i >> 1;
            const int idx = ((i & 1) << 8) | tid;
            const int r   = idx >> 2;
            const int c   = idx & 3;
            const __nv_bfloat16* src = (m < 2)
                ? srcA[m]     + (size_t)(gm0 + r) * DIM + ks * KC + c * 8
                : srcB[m - 2] + (size_t)(gn0 + r) * DIM + ks * KC + c * 8;
            const uint32_t dst = sbase + buf * STAGE + m * MAT + r * PSB + c * 16;
            CP_ASYNC16(dst, src);
        }
    };

    const int aRow = lane & 15;
    const int aCol = (lane >> 4) * 16;
    const int bRow = ((lane >> 4) & 1) * 8 + (lane & 7);
    const int bCol = ((lane >> 3) & 1) * 16;

    auto compute_stage = [&](int buf) {
        const uint32_t sb = sbase + buf * STAGE;
#pragma unroll
        for (int s = 0; s < 2; s++) {
            uint32_t la[16], lal[16], lbh[8], lbl[8];
            const int kb = s * 32;
#pragma unroll
            for (int i = 0; i < 4; i++)
                ldsm4(la + 4 * i, sb + 0 * MAT + (wm + 16 * i + aRow) * PSB + kb + aCol);
#pragma unroll
            for (int p = 0; p < 2; p++)
                ldsm4(lbh + 4 * p, sb + 2 * MAT + (wn + 16 * p + bRow) * PSB + kb + bCol);
#pragma unroll
            for (int i = 0; i < 4; i++)
#pragma unroll
                for (int j = 0; j < 4; j++)
                    mma_bf16(acc[i][j], la + 4 * i,
                             lbh[(j >> 1) * 4 + (j & 1) * 2], lbh[(j >> 1) * 4 + (j & 1) * 2 + 1]);
#pragma unroll
            for (int p = 0; p < 2; p++)
                ldsm4(lbl + 4 * p, sb + 3 * MAT + (wn + 16 * p + bRow) * PSB + kb + bCol);
#pragma unroll
            for (int i = 0; i < 4; i++)
#pragma unroll
                for (int j = 0; j < 4; j++)
                    mma_bf16(acc[i][j], la + 4 * i,
                             lbl[(j >> 1) * 4 + (j & 1) * 2], lbl[(j >> 1) * 4 + (j & 1) * 2 + 1]);
#pragma unroll
            for (int i = 0; i < 4; i++)
                ldsm4(lal + 4 * i, sb + 1 * MAT + (wm + 16 * i + aRow) * PSB + kb + aCol);
#pragma unroll
            for (int i = 0; i < 4; i++)
#pragma unroll
                for (int j = 0; j < 4; j++)
                    mma_bf16(acc[i][j], lal + 4 * i,
                             lbh[(j >> 1) * 4 + (j & 1) * 2], lbh[(j >> 1) * 4 + (j & 1) * 2 + 1]);
        }
    };

    load_stage(0, 0);
    CP_COMMIT();
    for (int ks = 0; ks < NS; ks++) {
        const int buf = ks & 1;
        if (ks + 1 < NS) {
            load_stage(ks + 1, buf ^ 1);
            CP_COMMIT();
            CP_WAIT(1);
        } else {
            CP_WAIT(0);
        }
        __syncthreads();
        compute_stage(buf);
        __syncthreads();
    }

#pragma unroll
    for (int i = 0; i < 4; i++) {
        const int r0 = gm0 + wm + 16 * i + (lane >> 2);
        const int r1 = r0 + 8;
#pragma unroll
        for (int j = 0; j < 4; j++) {
            const int col = gn0 + wn + 8 * j + 2 * (lane & 3);
            const float b0 = __ldg(&bias[col]);
            const float b1 = __ldg(&bias[col + 1]);
            if constexpr (sizeof(OutT) == 2) {
                __half2 v0 = __floats2half2_rn(acc[i][j][0] + b0, acc[i][j][1] + b1);
                __half2 v1 = __floats2half2_rn(acc[i][j][2] + b0, acc[i][j][3] + b1);
                *(__half2*)((__half*)C + (size_t)r0 * DIM + col) = v0;
                *(__half2*)((__half*)C + (size_t)r1 * DIM + col) = v1;
            } else {
                float2 v0 = make_float2(acc[i][j][0] + b0, acc[i][j][1] + b1);
                float2 v1 = make_float2(acc[i][j][2] + b0, acc[i][j][3] + b1);
                *(float2*)((float*)C + (size_t)r0 * DIM + col) = v0;
                *(float2*)((float*)C + (size_t)r1 * DIM + col) = v1;
            }
        }
    }
}

// ---------------- fast 2^t on the FMA pipe ----------------
__device__ __forceinline__ float fexp2(float t) {
    t = fmaxf(t, -126.f);
    float z = t + 12582912.f;
    int   n = __float_as_int(z);
    float f = t - (z - 12582912.f);
    float p = 1.33335581e-3f;
    p = fmaf(p, f, 9.61812911e-3f);
    p = fmaf(p, f, 5.55041087e-2f);
    p = fmaf(p, f, 2.40226507e-1f);
    p = fmaf(p, f, 6.93147182e-1f);
    p = fmaf(p, f, 1.0f);
    return __int_as_float(__float_as_int(p) + (n << 23));
}

// ---------------- tensor-core flash attention ----------------
// CTA: 64 queries (4 warps x 16 rows), K-tiles of 64. fp16 HMMA, fp32 accum.
#define ATSTR 72                        // padded row stride (halves)
#define ATILE (64 * ATSTR)              // halves per 64x64 tile
#define AQOFF 0
#define ATTN_SMEM (5 * ATILE * 2)       // Q + 2x(K,V) = 46080 B

__global__ __launch_bounds__(128) void attn_tc(
    const __half* __restrict__ Qg, const __half* __restrict__ Kg,
    const __half* __restrict__ Vg, float* __restrict__ O)
{
    extern __shared__ char smem[];
    const uint32_t sbase = smem_to_u32(smem);
    const int tid  = threadIdx.x;
    const int lane = tid & 31;
    const int w    = tid >> 5;
    const int qtile = blockIdx.x, h = blockIdx.y, b = blockIdx.z;
    const int q0 = qtile * 64;
    const size_t base = (size_t)b * SEQ * DIM + (size_t)h * HDIM;

    auto koff = [](int buf) { return ATILE + buf * 2 * ATILE; };
    auto voff = [](int buf) { return 2 * ATILE + buf * 2 * ATILE; };

    auto load_kv = [&](int kt, int buf) {
        const int k0 = kt * 64;
#pragma unroll
        for (int i = 0; i < 4; i++) {
            const int idx = i * 128 + tid;
            const int r = idx >> 3, c = idx & 7;
            const __half* g = Kg + base + (size_t)(k0 + r) * DIM + c * 8;
            const __half* gv = Vg + base + (size_t)(k0 + r) * DIM + c * 8;
            CP_ASYNC16(sbase + (koff(buf) + r * ATSTR + c * 8) * 2, g);
            CP_ASYNC16(sbase + (voff(buf) + r * ATSTR + c * 8) * 2, gv);
        }
    };

    // group 0: Q tile + KV tile 0
#pragma unroll
    for (int i = 0; i < 4; i++) {
        const int idx = i * 128 + tid;
        const int r = idx >> 3, c = idx & 7;
        CP_ASYNC16(sbase + (AQOFF + r * ATSTR + c * 8) * 2,
                   Qg + base + (size_t)(q0 + r) * DIM + c * 8);
    }
    load_kv(0, 0);
    CP_COMMIT();

    const int aRow  = lane & 15;
    const int aColB = (lane >> 4) * 16;
    const int bRow  = ((lane >> 4) & 1) * 8 + (lane & 7);
    const int bColB = ((lane >> 3) & 1) * 16;

    uint32_t qa[4][4];
    float m0 = -1e30f, m1 = -1e30f, l0 = 0.f, l1 = 0.f;
    float out[8][4];
#pragma unroll
    for (int j = 0; j < 8; j++)
#pragma unroll
        for (int f = 0; f < 4; f++) out[j][f] = 0.f;

    const float SC2 = 0.18033688011112042f;   // 0.125 * log2(e)

    for (int kt = 0; kt <= qtile; kt++) {
        const int buf = kt & 1;
        if (kt < qtile) {
            load_kv(kt + 1, buf ^ 1);
            CP_COMMIT();
            CP_WAIT(1);
        } else {
            CP_WAIT(0);
        }
        __syncthreads();

        if (kt == 0) {
#pragma unroll
            for (int c = 0; c < 4; c++)
                ldsm4(qa[c], sbase + ((AQOFF + (w * 16 + aRow) * ATSTR) * 2) + c * 32 + aColB);
        }

        // ---- QK^T ----
        const uint32_t kadr = sbase + koff(buf) * 2;
        float s[8][4];
#pragma unroll
        for (int j = 0; j < 8; j++)
#pragma unroll
            for (int f = 0; f < 4; f++) s[j][f] = 0.f;
#pragma unroll
        for (int c = 0; c < 4; c++) {
            uint32_t kb[16];
#pragma unroll
            for (int g = 0; g < 4; g++)
                ldsm4(kb + 4 * g, kadr + ((g * 16 + bRow) * ATSTR) * 2 + c * 32 + bColB);
#pragma unroll
            for (int j = 0; j < 8; j++)
                mma_f16(s[j], qa[c], kb[(j >> 1) * 4 + (j & 1) * 2],
                        kb[(j >> 1) * 4 + (j & 1) * 2 + 1]);
        }

        // scale into base-2 domain (+ causal mask on diagonal tile)
#pragma unroll
        for (int j = 0; j < 8; j++)
#pragma unroll
            for (int f = 0; f < 4; f++) s[j][f] *= SC2;
        if (kt == qtile) {
            const int r0 = w * 16 + (lane >> 2);
            const int r1 = r0 + 8;
#pragma unroll
            for (int j = 0; j < 8; j++) {
                const int ky = j * 8 + 2 * (lane & 3);
                if (ky     > r0) s[j][0] = -1e30f;
                if (ky + 1 > r0) s[j][1] = -1e30f;
                if (ky     > r1) s[j][2] = -1e30f;
                if (ky + 1 > r1) s[j][3] = -1e30f;
            }
        }

        // ---- online softmax (2 rows per thread) ----
        float mx0 = -1e30f, mx1 = -1e30f;
#pragma unroll
        for (int j = 0; j < 8; j++) {
            mx0 = fmaxf(mx0, fmaxf(s[j][0], s[j][1]));
            mx1 = fmaxf(mx1, fmaxf(s[j][2], s[j][3]));
        }
        mx0 = fmaxf(mx0, __shfl_xor_sync(0xffffffffu, mx0, 1));
        mx0 = fmaxf(mx0, __shfl_xor_sync(0xffffffffu, mx0, 2));
        mx1 = fmaxf(mx1, __shfl_xor_sync(0xffffffffu, mx1, 1));
        mx1 = fmaxf(mx1, __shfl_xor_sync(0xffffffffu, mx1, 2));
        const float nm0 = fmaxf(m0, mx0), nm1 = fmaxf(m1, mx1);
        const float cr0 = fexp2(m0 - nm0), cr1 = fexp2(m1 - nm1);
        m0 = nm0; m1 = nm1;

        float ls0 = 0.f, ls1 = 0.f;
        uint32_t pa[4][4];
#pragma unroll
        for (int c = 0; c < 4; c++) {
            const float p00 = fexp2(s[2 * c][0] - nm0);
            const float p01 = fexp2(s[2 * c][1] - nm0);
            const float p02 = fexp2(s[2 * c][2] - nm1);
            const float p03 = fexp2(s[2 * c][3] - nm1);
            const float p10 = fexp2(s[2 * c + 1][0] - nm0);
            const float p11 = fexp2(s[2 * c + 1][1] - nm0);
            const float p12 = fexp2(s[2 * c + 1][2] - nm1);
            const float p13 = fexp2(s[2 * c + 1][3] - nm1);
            ls0 += (p00 + p01) + (p10 + p11);
            ls1 += (p02 + p03) + (p12 + p13);
            pa[c][0] = packh2(p00, p01);
            pa[c][1] = packh2(p02, p03);
            pa[c][2] = packh2(p10, p11);
            pa[c][3] = packh2(p12, p13);
        }
        ls0 += __shfl_xor_sync(0xffffffffu, ls0, 1);
        ls0 += __shfl_xor_sync(0xffffffffu, ls0, 2);
        ls1 += __shfl_xor_sync(0xffffffffu, ls1, 1);
        ls1 += __shfl_xor_sync(0xffffffffu, ls1, 2);
        l0 = l0 * cr0 + ls0;
        l1 = l1 * cr1 + ls1;
#pragma unroll
        for (int j = 0; j < 8; j++) {
            out[j][0] *= cr0; out[j][1] *= cr0;
            out[j][2] *= cr1; out[j][3] *= cr1;
        }

        // ---- P @ V ----
        const uint32_t vadr = sbase + voff(buf) * 2;
#pragma unroll
        for (int c = 0; c < 4; c++) {
            uint32_t vb[16];
#pragma unroll
            for (int dg = 0; dg < 4; dg++)
                ldsm4t(vb + 4 * dg,
                       vadr + ((c * 16 + (lane & 15)) * ATSTR) * 2
                            + (dg * 16 + (lane >> 4) * 8) * 2);
#pragma unroll
            for (int j = 0; j < 8; j++)
                mma_f16(out[j], pa[c], vb[(j >> 1) * 4 + (j & 1) * 2],
                        vb[(j >> 1) * 4 + (j & 1) * 2 + 1]);
        }
        __syncthreads();
    }

    // ---- normalize + store fp32 ----
    const float inv0 = 1.f / l0, inv1 = 1.f / l1;
    const int r0 = q0 + w * 16 + (lane >> 2);
    float* o0 = O + base + (size_t)r0 * DIM;
    float* o1 = o0 + (size_t)8 * DIM;
#pragma unroll
    for (int j = 0; j < 8; j++) {
        const int cc = j * 8 + 2 * (lane & 3);
        float2 v0 = make_float2(out[j][0] * inv0, out[j][1] * inv0);
        float2 v1 = make_float2(out[j][2] * inv1, out[j][3] * inv1);
        *(float2*)(o0 + cc) = v0;
        *(float2*)(o1 + cc) = v1;
    }
}

// ---------------- launch ----------------
extern "C" void kernel_launch(void* const* d_in, const int* in_sizes, int n_in,
                              void* d_out, int out_size)
{
    const float* q  = (const float*)d_in[0];
    const float* Wq = (const float*)d_in[2];
    const float* bq = (const float*)d_in[3];
    const float* Wk = (const float*)d_in[4];
    const float* bk = (const float*)d_in[5];
    const float* Wv = (const float*)d_in[6];
    const float* bv = (const float*)d_in[7];
    const float* Wo = (const float*)d_in[8];
    const float* bo = (const float*)d_in[9];
    float* out = (float*)d_out;

    float* Cb;
    __half *Qh, *Kh, *Vh;
    __nv_bfloat16 *xhi, *xlo, *whi, *wlo;
    cudaGetSymbolAddress((void**)&Cb, g_C);
    cudaGetSymbolAddress((void**)&Qh, g_Qh);
    cudaGetSymbolAddress((void**)&Kh, g_Kh);
    cudaGetSymbolAddress((void**)&Vh, g_Vh);
    cudaGetSymbolAddress((void**)&xhi, g_xhi);
    cudaGetSymbolAddress((void**)&xlo, g_xlo);
    cudaGetSymbolAddress((void**)&whi, g_whi);
    cudaGetSymbolAddress((void**)&wlo, g_wlo);

    cudaFuncSetAttribute(gemm_tc<__half>, cudaFuncAttributeMaxDynamicSharedMemorySize, GEMM_SMEM);
    cudaFuncSetAttribute(gemm_tc<float>,  cudaFuncAttributeMaxDynamicSharedMemorySize, GEMM_SMEM);
    cudaFuncSetAttribute(attn_tc, cudaFuncAttributeMaxDynamicSharedMemorySize, ATTN_SMEM);

    const int nX4 = MROWS * DIM / 4;
    const int nW4 = DIM * DIM / 4;

    split_kernel<<<nX4 / 256, 256>>>(q, xhi, xlo, nX4);
    split_kernel<<<nW4 / 256, 256>>>(Wq, whi + 0 * (size_t)DIM * DIM, wlo + 0 * (size_t)DIM * DIM, nW4);
    split_kernel<<<nW4 / 256, 256>>>(Wk, whi + 1 * (size_t)DIM * DIM, wlo + 1 * (size_t)DIM * DIM, nW4);
    split_kernel<<<nW4 / 256, 256>>>(Wv, whi + 2 * (size_t)DIM * DIM, wlo + 2 * (size_t)DIM * DIM, nW4);
    split_kernel<<<nW4 / 256, 256>>>(Wo, whi + 3 * (size_t)DIM * DIM, wlo + 3 * (size_t)DIM * DIM, nW4);

    const dim3 ggrid(DIM / 128, MROWS / 128);   // (8, 64)
    gemm_tc<__half><<<ggrid, 256, GEMM_SMEM>>>(xhi, xlo, whi + 0 * (size_t)DIM * DIM, wlo + 0 * (size_t)DIM * DIM, bq, Qh);
    gemm_tc<__half><<<ggrid, 256, GEMM_SMEM>>>(xhi, xlo, whi + 1 * (size_t)DIM * DIM, wlo + 1 * (size_t)DIM * DIM, bk, Kh);
    gemm_tc<__half><<<ggrid, 256, GEMM_SMEM>>>(xhi, xlo, whi + 2 * (size_t)DIM * DIM, wlo + 2 * (size_t)DIM * DIM, bv, Vh);

    const dim3 agrid(SEQ / 64, HEADS, BATCH);   // (32, 16, 4)
    attn_tc<<<agrid, 128, ATTN_SMEM>>>(Qh, Kh, Vh, Cb);

    split_kernel<<<nX4 / 256, 256>>>(Cb, xhi, xlo, nX4);
    gemm_tc<float><<<ggrid, 256, GEMM_SMEM>>>(xhi, xlo, whi + 3 * (size_t)DIM * DIM, wlo + 3 * (size_t)DIM * DIM, bo, out);
}

// round 9
// speedup vs baseline: 10.7760x; 2.9318x over previous
#include <cuda_runtime.h>
#include <cuda_fp16.h>
#include <cstdint>
#include <math.h>

// ---------------- problem constants ----------------
#define BATCH 4
#define SEQ   2048
#define DIM   1024
#define HEADS 16
#define HDIM  64
#define MROWS (BATCH * SEQ)   // 8192

// ---------------- scratch (device globals; no allocs allowed) ----------------
__device__ float  g_C[MROWS * DIM];        // attention output (fp32)
__device__ __half g_Qh[MROWS * DIM];       // projected Q/K/V (fp16)
__device__ __half g_Kh[MROWS * DIM];
__device__ __half g_Vh[MROWS * DIM];
__device__ __half g_xh[MROWS * DIM];       // fp16 activations (q, later C)
__device__ __half g_wh[4][DIM * DIM];      // fp16 weights

// ---------------- small helpers ----------------
__device__ __forceinline__ uint32_t smem_to_u32(const void* p) {
    uint32_t a;
    asm("{ .reg .u64 t; cvta.to.shared.u64 t, %1; cvt.u32.u64 %0, t; }" : "=r"(a) : "l"(p));
    return a;
}
__device__ __forceinline__ void ldsm4(uint32_t* r, uint32_t addr) {
    asm volatile("ldmatrix.sync.aligned.m8n8.x4.shared.b16 {%0,%1,%2,%3}, [%4];"
                 : "=r"(r[0]), "=r"(r[1]), "=r"(r[2]), "=r"(r[3]) : "r"(addr));
}
__device__ __forceinline__ void ldsm4t(uint32_t* r, uint32_t addr) {
    asm volatile("ldmatrix.sync.aligned.m8n8.x4.trans.shared.b16 {%0,%1,%2,%3}, [%4];"
                 : "=r"(r[0]), "=r"(r[1]), "=r"(r[2]), "=r"(r[3]) : "r"(addr));
}
__device__ __forceinline__ void mma_f16(float* c, const uint32_t* a, uint32_t b0, uint32_t b1) {
    asm volatile("mma.sync.aligned.m16n8k16.row.col.f32.f16.f16.f32 "
                 "{%0,%1,%2,%3}, {%4,%5,%6,%7}, {%8,%9}, {%0,%1,%2,%3};"
                 : "+f"(c[0]), "+f"(c[1]), "+f"(c[2]), "+f"(c[3])
                 : "r"(a[0]), "r"(a[1]), "r"(a[2]), "r"(a[3]), "r"(b0), "r"(b1));
}
__device__ __forceinline__ uint32_t packh2(float a, float b) {
    __half2 h = __floats2half2_rn(a, b);
    return *reinterpret_cast<uint32_t*>(&h);
}
#define CP_ASYNC16(dst, src) \
    asm volatile("cp.async.cg.shared.global [%0], [%1], 16;" :: "r"(dst), "l"(src) : "memory")
#define CP_COMMIT() asm volatile("cp.async.commit_group;" ::: "memory")
#define CP_WAIT(n)  asm volatile("cp.async.wait_group %0;" :: "n"(n) : "memory")

// ---------------- convert fp32 -> fp16 ----------------
__global__ __launch_bounds__(256) void cvt_kernel(
    const float* __restrict__ x, __half* __restrict__ y, int n4)
{
    int i = blockIdx.x * blockDim.x + threadIdx.x;
    if (i >= n4) return;
    float4 v = ((const float4*)x)[i];
    __half2 h0 = __floats2half2_rn(v.x, v.y);
    __half2 h1 = __floats2half2_rn(v.z, v.w);
    uint2 o;
    o.x = *reinterpret_cast<uint32_t*>(&h0);
    o.y = *reinterpret_cast<uint32_t*>(&h1);
    ((uint2*)y)[i] = o;
}

// ---------------- single-pass fp16 HMMA GEMM: C = A @ W^T + bias ----------------
// A: [8192,1024] fp16, W: [1024,1024] fp16 row-major (K contiguous).
// Block tile 128x128, K-chunk 64, double-buffered cp.async.
// 8 warps, each 64x32 (m16n8k16 atoms: 4 x 4).
#define KC 64
#define NS (DIM / KC)            // 16 stages
#define PSB 144                  // padded row stride bytes (128 data + 16 pad)
#define MAT (128 * PSB)          // 18432 B per matrix tile
#define STAGE (2 * MAT)          // A, B
#define GEMM_SMEM (2 * STAGE)    // 73728 B

template <typename OutT>
__global__ __launch_bounds__(256, 1) void gemm_h(
    const __half* __restrict__ A, const __half* __restrict__ B,
    const float* __restrict__ bias, OutT* __restrict__ C)
{
    extern __shared__ char smem[];
    const uint32_t sbase = smem_to_u32(smem);
    const int tid  = threadIdx.x;
    const int wid  = tid >> 5;
    const int lane = tid & 31;
    const int gm0 = blockIdx.y * 128;
    const int gn0 = blockIdx.x * 128;
    const int wm = (wid >> 2) * 64;   // 0 or 64
    const int wn = (wid & 3) * 32;    // 0,32,64,96

    float acc[4][4][4];
#pragma unroll
    for (int i = 0; i < 4; i++)
#pragma unroll
        for (int j = 0; j < 4; j++)
#pragma unroll
            for (int f = 0; f < 4; f++) acc[i][j][f] = 0.f;

    // stage load: 2 matrices x 128 rows x 128B = 2048 x 16B, 8 per thread
    auto load_stage = [&](int ks, int buf) {
#pragma unroll
        for (int i = 0; i < 8; i++) {
            const int m   = i >> 2;                     // 0:A 1:B
            const int rem = ((i & 3) << 8) | tid;       // 0..1023
            const int r   = rem >> 3;                   // 0..127
            const int c   = rem & 7;                    // 16B unit
            const __half* src = (m == 0)
                ? A + (size_t)(gm0 + r) * DIM + ks * KC + c * 8
                : B + (size_t)(gn0 + r) * DIM + ks * KC + c * 8;
            CP_ASYNC16(sbase + buf * STAGE + m * MAT + r * PSB + c * 16, src);
        }
    };

    const int aRow = lane & 15;
    const int aCol = (lane >> 4) * 16;
    const int bRow = ((lane >> 4) & 1) * 8 + (lane & 7);
    const int bCol = ((lane >> 3) & 1) * 16;

    auto compute_stage = [&](int buf) {
        const uint32_t sb = sbase + buf * STAGE;
#pragma unroll
        for (int s = 0; s < 4; s++) {                    // 4 x k16
            const int kb = s * 32;
            uint32_t la[16], lb[8];
#pragma unroll
            for (int i = 0; i < 4; i++)
                ldsm4(la + 4 * i, sb + 0 * MAT + (wm + 16 * i + aRow) * PSB + kb + aCol);
#pragma unroll
            for (int p = 0; p < 2; p++)
                ldsm4(lb + 4 * p, sb + 1 * MAT + (wn + 16 * p + bRow) * PSB + kb + bCol);
#pragma unroll
            for (int i = 0; i < 4; i++)
#pragma unroll
                for (int j = 0; j < 4; j++)
                    mma_f16(acc[i][j], la + 4 * i,
                            lb[(j >> 1) * 4 + (j & 1) * 2], lb[(j >> 1) * 4 + (j & 1) * 2 + 1]);
        }
    };

    load_stage(0, 0);
    CP_COMMIT();
    for (int ks = 0; ks < NS; ks++) {
        const int buf = ks & 1;
        if (ks + 1 < NS) {
            load_stage(ks + 1, buf ^ 1);
            CP_COMMIT();
            CP_WAIT(1);
        } else {
            CP_WAIT(0);
        }
        __syncthreads();
        compute_stage(buf);
        __syncthreads();
    }

    // epilogue: direct stores with bias
#pragma unroll
    for (int i = 0; i < 4; i++) {
        const int r0 = gm0 + wm + 16 * i + (lane >> 2);
        const int r1 = r0 + 8;
#pragma unroll
        for (int j = 0; j < 4; j++) {
            const int col = gn0 + wn + 8 * j + 2 * (lane & 3);
            const float b0 = __ldg(&bias[col]);
            const float b1 = __ldg(&bias[col + 1]);
            if constexpr (sizeof(OutT) == 2) {
                __half2 v0 = __floats2half2_rn(acc[i][j][0] + b0, acc[i][j][1] + b1);
                __half2 v1 = __floats2half2_rn(acc[i][j][2] + b0, acc[i][j][3] + b1);
                *(__half2*)((__half*)C + (size_t)r0 * DIM + col) = v0;
                *(__half2*)((__half*)C + (size_t)r1 * DIM + col) = v1;
            } else {
                float2 v0 = make_float2(acc[i][j][0] + b0, acc[i][j][1] + b1);
                float2 v1 = make_float2(acc[i][j][2] + b0, acc[i][j][3] + b1);
                *(float2*)((float*)C + (size_t)r0 * DIM + col) = v0;
                *(float2*)((float*)C + (size_t)r1 * DIM + col) = v1;
            }
        }
    }
}

// ---------------- fast 2^t on the FMA pipe ----------------
__device__ __forceinline__ float fexp2(float t) {
    t = fmaxf(t, -126.f);
    float z = t + 12582912.f;
    int   n = __float_as_int(z);
    float f = t - (z - 12582912.f);
    float p = 1.33335581e-3f;
    p = fmaf(p, f, 9.61812911e-3f);
    p = fmaf(p, f, 5.55041087e-2f);
    p = fmaf(p, f, 2.40226507e-1f);
    p = fmaf(p, f, 6.93147182e-1f);
    p = fmaf(p, f, 1.0f);
    return __int_as_float(__float_as_int(p) + (n << 23));
}

// ---------------- tensor-core flash attention (unchanged from R6) ----------------
#define ATSTR 72
#define ATILE (64 * ATSTR)
#define AQOFF 0
#define ATTN_SMEM (5 * ATILE * 2)   // 46080 B

__global__ __launch_bounds__(128) void attn_tc(
    const __half* __restrict__ Qg, const __half* __restrict__ Kg,
    const __half* __restrict__ Vg, float* __restrict__ O)
{
    extern __shared__ char smem[];
    const uint32_t sbase = smem_to_u32(smem);
    const int tid  = threadIdx.x;
    const int lane = tid & 31;
    const int w    = tid >> 5;
    const int qtile = blockIdx.x, h = blockIdx.y, b = blockIdx.z;
    const int q0 = qtile * 64;
    const size_t base = (size_t)b * SEQ * DIM + (size_t)h * HDIM;

    auto koff = [](int buf) { return ATILE + buf * 2 * ATILE; };
    auto voff = [](int buf) { return 2 * ATILE + buf * 2 * ATILE; };

    auto load_kv = [&](int kt, int buf) {
        const int k0 = kt * 64;
#pragma unroll
        for (int i = 0; i < 4; i++) {
            const int idx = i * 128 + tid;
            const int r = idx >> 3, c = idx & 7;
            CP_ASYNC16(sbase + (koff(buf) + r * ATSTR + c * 8) * 2,
                       Kg + base + (size_t)(k0 + r) * DIM + c * 8);
            CP_ASYNC16(sbase + (voff(buf) + r * ATSTR + c * 8) * 2,
                       Vg + base + (size_t)(k0 + r) * DIM + c * 8);
        }
    };

#pragma unroll
    for (int i = 0; i < 4; i++) {
        const int idx = i * 128 + tid;
        const int r = idx >> 3, c = idx & 7;
        CP_ASYNC16(sbase + (AQOFF + r * ATSTR + c * 8) * 2,
                   Qg + base + (size_t)(q0 + r) * DIM + c * 8);
    }
    load_kv(0, 0);
    CP_COMMIT();

    const int aRow  = lane & 15;
    const int aColB = (lane >> 4) * 16;
    const int bRow  = ((lane >> 4) & 1) * 8 + (lane & 7);
    const int bColB = ((lane >> 3) & 1) * 16;

    uint32_t qa[4][4];
    float m0 = -1e30f, m1 = -1e30f, l0 = 0.f, l1 = 0.f;
    float out[8][4];
#pragma unroll
    for (int j = 0; j < 8; j++)
#pragma unroll
        for (int f = 0; f < 4; f++) out[j][f] = 0.f;

    const float SC2 = 0.18033688011112042f;   // 0.125 * log2(e)

    for (int kt = 0; kt <= qtile; kt++) {
        const int buf = kt & 1;
        if (kt < qtile) {
            load_kv(kt + 1, buf ^ 1);
            CP_COMMIT();
            CP_WAIT(1);
        } else {
            CP_WAIT(0);
        }
        __syncthreads();

        if (kt == 0) {
#pragma unroll
            for (int c = 0; c < 4; c++)
                ldsm4(qa[c], sbase + ((AQOFF + (w * 16 + aRow) * ATSTR) * 2) + c * 32 + aColB);
        }

        const uint32_t kadr = sbase + koff(buf) * 2;
        float s[8][4];
#pragma unroll
        for (int j = 0; j < 8; j++)
#pragma unroll
            for (int f = 0; f < 4; f++) s[j][f] = 0.f;
#pragma unroll
        for (int c = 0; c < 4; c++) {
            uint32_t kb[16];
#pragma unroll
            for (int g = 0; g < 4; g++)
                ldsm4(kb + 4 * g, kadr + ((g * 16 + bRow) * ATSTR) * 2 + c * 32 + bColB);
#pragma unroll
            for (int j = 0; j < 8; j++)
                mma_f16(s[j], qa[c], kb[(j >> 1) * 4 + (j & 1) * 2],
                        kb[(j >> 1) * 4 + (j & 1) * 2 + 1]);
        }

#pragma unroll
        for (int j = 0; j < 8; j++)
#pragma unroll
            for (int f = 0; f < 4; f++) s[j][f] *= SC2;
        if (kt == qtile) {
            const int r0 = w * 16 + (lane >> 2);
            const int r1 = r0 + 8;
#pragma unroll
            for (int j = 0; j < 8; j++) {
                const int ky = j * 8 + 2 * (lane & 3);
                if (ky     > r0) s[j][0] = -1e30f;
                if (ky + 1 > r0) s[j][1] = -1e30f;
                if (ky     > r1) s[j][2] = -1e30f;
                if (ky + 1 > r1) s[j][3] = -1e30f;
            }
        }

        float mx0 = -1e30f, mx1 = -1e30f;
#pragma unroll
        for (int j = 0; j < 8; j++) {
            mx0 = fmaxf(mx0, fmaxf(s[j][0], s[j][1]));
            mx1 = fmaxf(mx1, fmaxf(s[j][2], s[j][3]));
        }
        mx0 = fmaxf(mx0, __shfl_xor_sync(0xffffffffu, mx0, 1));
        mx0 = fmaxf(mx0, __shfl_xor_sync(0xffffffffu, mx0, 2));
        mx1 = fmaxf(mx1, __shfl_xor_sync(0xffffffffu, mx1, 1));
        mx1 = fmaxf(mx1, __shfl_xor_sync(0xffffffffu, mx1, 2));
        const float nm0 = fmaxf(m0, mx0), nm1 = fmaxf(m1, mx1);
        const float cr0 = fexp2(m0 - nm0), cr1 = fexp2(m1 - nm1);
        m0 = nm0; m1 = nm1;

        float ls0 = 0.f, ls1 = 0.f;
        uint32_t pa[4][4];
#pragma unroll
        for (int c = 0; c < 4; c++) {
            const float p00 = fexp2(s[2 * c][0] - nm0);
            const float p01 = fexp2(s[2 * c][1] - nm0);
            const float p02 = fexp2(s[2 * c][2] - nm1);
            const float p03 = fexp2(s[2 * c][3] - nm1);
            const float p10 = fexp2(s[2 * c + 1][0] - nm0);
            const float p11 = fexp2(s[2 * c + 1][1] - nm0);
            const float p12 = fexp2(s[2 * c + 1][2] - nm1);
            const float p13 = fexp2(s[2 * c + 1][3] - nm1);
            ls0 += (p00 + p01) + (p10 + p11);
            ls1 += (p02 + p03) + (p12 + p13);
            pa[c][0] = packh2(p00, p01);
            pa[c][1] = packh2(p02, p03);
            pa[c][2] = packh2(p10, p11);
            pa[c][3] = packh2(p12, p13);
        }
        ls0 += __shfl_xor_sync(0xffffffffu, ls0, 1);
        ls0 += __shfl_xor_sync(0xffffffffu, ls0, 2);
        ls1 += __shfl_xor_sync(0xffffffffu, ls1, 1);
        ls1 += __shfl_xor_sync(0xffffffffu, ls1, 2);
        l0 = l0 * cr0 + ls0;
        l1 = l1 * cr1 + ls1;
#pragma unroll
        for (int j = 0; j < 8; j++) {
            out[j][0] *= cr0; out[j][1] *= cr0;
            out[j][2] *= cr1; out[j][3] *= cr1;
        }

        const uint32_t vadr = sbase + voff(buf) * 2;
#pragma unroll
        for (int c = 0; c < 4; c++) {
            uint32_t vb[16];
#pragma unroll
            for (int dg = 0; dg < 4; dg++)
                ldsm4t(vb + 4 * dg,
                       vadr + ((c * 16 + (lane & 15)) * ATSTR) * 2
                            + (dg * 16 + (lane >> 4) * 8) * 2);
#pragma unroll
            for (int j = 0; j < 8; j++)
                mma_f16(out[j], pa[c], vb[(j >> 1) * 4 + (j & 1) * 2],
                        vb[(j >> 1) * 4 + (j & 1) * 2 + 1]);
        }
        __syncthreads();
    }

    const float inv0 = 1.f / l0, inv1 = 1.f / l1;
    const int r0 = q0 + w * 16 + (lane >> 2);
    float* o0 = O + base + (size_t)r0 * DIM;
    float* o1 = o0 + (size_t)8 * DIM;
#pragma unroll
    for (int j = 0; j < 8; j++) {
        const int cc = j * 8 + 2 * (lane & 3);
        float2 v0 = make_float2(out[j][0] * inv0, out[j][1] * inv0);
        float2 v1 = make_float2(out[j][2] * inv1, out[j][3] * inv1);
        *(float2*)(o0 + cc) = v0;
        *(float2*)(o1 + cc) = v1;
    }
}

// ---------------- launch ----------------
extern "C" void kernel_launch(void* const* d_in, const int* in_sizes, int n_in,
                              void* d_out, int out_size)
{
    const float* q  = (const float*)d_in[0];
    const float* Wq = (const float*)d_in[2];
    const float* bq = (const float*)d_in[3];
    const float* Wk = (const float*)d_in[4];
    const float* bk = (const float*)d_in[5];
    const float* Wv = (const float*)d_in[6];
    const float* bv = (const float*)d_in[7];
    const float* Wo = (const float*)d_in[8];
    const float* bo = (const float*)d_in[9];
    float* out = (float*)d_out;

    float* Cb;
    __half *Qh, *Kh, *Vh, *xh, *wh;
    cudaGetSymbolAddress((void**)&Cb, g_C);
    cudaGetSymbolAddress((void**)&Qh, g_Qh);
    cudaGetSymbolAddress((void**)&Kh, g_Kh);
    cudaGetSymbolAddress((void**)&Vh, g_Vh);
    cudaGetSymbolAddress((void**)&xh, g_xh);
    cudaGetSymbolAddress((void**)&wh, g_wh);

    cudaFuncSetAttribute(gemm_h<__half>, cudaFuncAttributeMaxDynamicSharedMemorySize, GEMM_SMEM);
    cudaFuncSetAttribute(gemm_h<float>,  cudaFuncAttributeMaxDynamicSharedMemorySize, GEMM_SMEM);
    cudaFuncSetAttribute(attn_tc, cudaFuncAttributeMaxDynamicSharedMemorySize, ATTN_SMEM);

    const int nX4 = MROWS * DIM / 4;   // 2097152
    const int nW4 = DIM * DIM / 4;     // 262144

    cvt_kernel<<<nX4 / 256, 256>>>(q, xh, nX4);
    cvt_kernel<<<nW4 / 256, 256>>>(Wq, wh + 0 * (size_t)DIM * DIM, nW4);
    cvt_kernel<<<nW4 / 256, 256>>>(Wk, wh + 1 * (size_t)DIM * DIM, nW4);
    cvt_kernel<<<nW4 / 256, 256>>>(Wv, wh + 2 * (size_t)DIM * DIM, nW4);
    cvt_kernel<<<nW4 / 256, 256>>>(Wo, wh + 3 * (size_t)DIM * DIM, nW4);

    const dim3 ggrid(DIM / 128, MROWS / 128);   // (8, 64)
    gemm_h<__half><<<ggrid, 256, GEMM_SMEM>>>(xh, wh + 0 * (size_t)DIM * DIM, bq, Qh);
    gemm_h<__half><<<ggrid, 256, GEMM_SMEM>>>(xh, wh + 1 * (size_t)DIM * DIM, bk, Kh);
    gemm_h<__half><<<ggrid, 256, GEMM_SMEM>>>(xh, wh + 2 * (size_t)DIM * DIM, bv, Vh);

    const dim3 agrid(SEQ / 64, HEADS, BATCH);   // (32, 16, 4)
    attn_tc<<<agrid, 128, ATTN_SMEM>>>(Qh, Kh, Vh, Cb);

    cvt_kernel<<<nX4 / 256, 256>>>(Cb, xh, nX4);
    gemm_h<float><<<ggrid, 256, GEMM_SMEM>>>(xh, wh + 3 * (size_t)DIM * DIM, bo, out);
}

// round 12
// speedup vs baseline: 12.7800x; 1.1860x over previous
#include <cuda_runtime.h>
#include <cuda_fp16.h>
#include <cstdint>
#include <math.h>

// ---------------- problem constants ----------------
#define BATCH 4
#define SEQ   2048
#define DIM   1024
#define HEADS 16
#define HDIM  64
#define MROWS (BATCH * SEQ)   // 8192

// ---------------- scratch (device globals; no allocs allowed) ----------------
__device__ __half g_Qh[MROWS * DIM];       // projected Q/K/V (fp16)
__device__ __half g_Kh[MROWS * DIM];
__device__ __half g_Vh[MROWS * DIM];
__device__ __half g_xh[MROWS * DIM];       // fp16 activations (q, then attn out)
__device__ __half g_wh[4][DIM * DIM];      // fp16 weights

// ---------------- small helpers ----------------
__device__ __forceinline__ uint32_t smem_to_u32(const void* p) {
    uint32_t a;
    asm("{ .reg .u64 t; cvta.to.shared.u64 t, %1; cvt.u32.u64 %0, t; }" : "=r"(a) : "l"(p));
    return a;
}
__device__ __forceinline__ void ldsm4(uint32_t* r, uint32_t addr) {
    asm volatile("ldmatrix.sync.aligned.m8n8.x4.shared.b16 {%0,%1,%2,%3}, [%4];"
                 : "=r"(r[0]), "=r"(r[1]), "=r"(r[2]), "=r"(r[3]) : "r"(addr));
}
__device__ __forceinline__ void ldsm4t(uint32_t* r, uint32_t addr) {
    asm volatile("ldmatrix.sync.aligned.m8n8.x4.trans.shared.b16 {%0,%1,%2,%3}, [%4];"
                 : "=r"(r[0]), "=r"(r[1]), "=r"(r[2]), "=r"(r[3]) : "r"(addr));
}
__device__ __forceinline__ void mma_f16(float* c, const uint32_t* a, uint32_t b0, uint32_t b1) {
    asm volatile("mma.sync.aligned.m16n8k16.row.col.f32.f16.f16.f32 "
                 "{%0,%1,%2,%3}, {%4,%5,%6,%7}, {%8,%9}, {%0,%1,%2,%3};"
                 : "+f"(c[0]), "+f"(c[1]), "+f"(c[2]), "+f"(c[3])
                 : "r"(a[0]), "r"(a[1]), "r"(a[2]), "r"(a[3]), "r"(b0), "r"(b1));
}
__device__ __forceinline__ uint32_t packh2(float a, float b) {
    __half2 h = __floats2half2_rn(a, b);
    return *reinterpret_cast<uint32_t*>(&h);
}
#define CP_ASYNC16(dst, src) \
    asm volatile("cp.async.cg.shared.global [%0], [%1], 16;" :: "r"(dst), "l"(src) : "memory")
#define CP_COMMIT() asm volatile("cp.async.commit_group;" ::: "memory")
#define CP_WAIT(n)  asm volatile("cp.async.wait_group %0;" :: "n"(n) : "memory")

// ---------------- converts ----------------
__global__ __launch_bounds__(256) void cvt_kernel(
    const float* __restrict__ x, __half* __restrict__ y, int n4)
{
    int i = blockIdx.x * blockDim.x + threadIdx.x;
    if (i >= n4) return;
    float4 v = ((const float4*)x)[i];
    __half2 h0 = __floats2half2_rn(v.x, v.y);
    __half2 h1 = __floats2half2_rn(v.z, v.w);
    uint2 o;
    o.x = *reinterpret_cast<uint32_t*>(&h0);
    o.y = *reinterpret_cast<uint32_t*>(&h1);
    ((uint2*)y)[i] = o;
}

// all 4 weights in one launch; blockIdx.y selects the segment
__global__ __launch_bounds__(256) void cvt4_kernel(
    const float* __restrict__ w0, const float* __restrict__ w1,
    const float* __restrict__ w2, const float* __restrict__ w3,
    __half* __restrict__ dst, int n4)
{
    int i = blockIdx.x * blockDim.x + threadIdx.x;
    if (i >= n4) return;
    const int seg = blockIdx.y;
    const float* src = (seg == 0) ? w0 : (seg == 1) ? w1 : (seg == 2) ? w2 : w3;
    float4 v = ((const float4*)src)[i];
    __half2 h0 = __floats2half2_rn(v.x, v.y);
    __half2 h1 = __floats2half2_rn(v.z, v.w);
    uint2 o;
    o.x = *reinterpret_cast<uint32_t*>(&h0);
    o.y = *reinterpret_cast<uint32_t*>(&h1);
    ((uint2*)(dst + (size_t)seg * DIM * DIM))[i] = o;
}

// ---------------- single-pass fp16 HMMA GEMM core ----------------
// Block tile 128x128, K-chunk 64, double-buffered cp.async, occupancy 2.
#define KC 64
#define NS (DIM / KC)            // 16 stages
#define PSB 144                  // padded row stride bytes
#define MAT (128 * PSB)          // 18432 B
#define STAGE (2 * MAT)
#define GEMM_SMEM (2 * STAGE)    // 73728 B

template <typename OutT>
__device__ __forceinline__ void gemm_body(
    const __half* __restrict__ A, const __half* __restrict__ B,
    const float* __restrict__ bias, OutT* __restrict__ C,
    int gm0, int gn0, char* smem)
{
    const uint32_t sbase = smem_to_u32(smem);
    const int tid  = threadIdx.x;
    const int wid  = tid >> 5;
    const int lane = tid & 31;
    const int wm = (wid >> 2) * 64;
    const int wn = (wid & 3) * 32;

    float acc[4][4][4];
#pragma unroll
    for (int i = 0; i < 4; i++)
#pragma unroll
        for (int j = 0; j < 4; j++)
#pragma unroll
            for (int f = 0; f < 4; f++) acc[i][j][f] = 0.f;

    auto load_stage = [&](int ks, int buf) {
#pragma unroll
        for (int i = 0; i < 8; i++) {
            const int m   = i >> 2;                     // 0:A 1:B
            const int rem = ((i & 3) << 8) | tid;
            const int r   = rem >> 3;
            const int c   = rem & 7;
            const __half* src = (m == 0)
                ? A + (size_t)(gm0 + r) * DIM + ks * KC + c * 8
                : B + (size_t)(gn0 + r) * DIM + ks * KC + c * 8;
            CP_ASYNC16(sbase + buf * STAGE + m * MAT + r * PSB + c * 16, src);
        }
    };

    const int aRow = lane & 15;
    const int aCol = (lane >> 4) * 16;
    const int bRow = ((lane >> 4) & 1) * 8 + (lane & 7);
    const int bCol = ((lane >> 3) & 1) * 16;

    auto compute_stage = [&](int buf) {
        const uint32_t sb = sbase + buf * STAGE;
#pragma unroll
        for (int s = 0; s < 4; s++) {
            const int kb = s * 32;
            uint32_t la[16], lb[8];
#pragma unroll
            for (int i = 0; i < 4; i++)
                ldsm4(la + 4 * i, sb + 0 * MAT + (wm + 16 * i + aRow) * PSB + kb + aCol);
#pragma unroll
            for (int p = 0; p < 2; p++)
                ldsm4(lb + 4 * p, sb + 1 * MAT + (wn + 16 * p + bRow) * PSB + kb + bCol);
#pragma unroll
            for (int i = 0; i < 4; i++)
#pragma unroll
                for (int j = 0; j < 4; j++)
                    mma_f16(acc[i][j], la + 4 * i,
                            lb[(j >> 1) * 4 + (j & 1) * 2], lb[(j >> 1) * 4 + (j & 1) * 2 + 1]);
        }
    };

    load_stage(0, 0);
    CP_COMMIT();
    for (int ks = 0; ks < NS; ks++) {
        const int buf = ks & 1;
        if (ks + 1 < NS) {
            load_stage(ks + 1, buf ^ 1);
            CP_COMMIT();
            CP_WAIT(1);
        } else {
            CP_WAIT(0);
        }
        __syncthreads();
        compute_stage(buf);
        __syncthreads();
    }

#pragma unroll
    for (int i = 0; i < 4; i++) {
        const int r0 = gm0 + wm + 16 * i + (lane >> 2);
        const int r1 = r0 + 8;
#pragma unroll
        for (int j = 0; j < 4; j++) {
            const int col = gn0 + wn + 8 * j + 2 * (lane & 3);
            const float b0 = __ldg(&bias[col]);
            const float b1 = __ldg(&bias[col + 1]);
            if constexpr (sizeof(OutT) == 2) {
                __half2 v0 = __floats2half2_rn(acc[i][j][0] + b0, acc[i][j][1] + b1);
                __half2 v1 = __floats2half2_rn(acc[i][j][2] + b0, acc[i][j][3] + b1);
                *(__half2*)((__half*)C + (size_t)r0 * DIM + col) = v0;
                *(__half2*)((__half*)C + (size_t)r1 * DIM + col) = v1;
            } else {
                float2 v0 = make_float2(acc[i][j][0] + b0, acc[i][j][1] + b1);
                float2 v1 = make_float2(acc[i][j][2] + b0, acc[i][j][3] + b1);
                *(float2*)((float*)C + (size_t)r0 * DIM + col) = v0;
                *(float2*)((float*)C + (size_t)r1 * DIM + col) = v1;
            }
        }
    }
}

// merged Q/K/V projection: blockIdx.z selects weight/bias/output
__global__ __launch_bounds__(256, 2) void gemm_qkv(
    const __half* __restrict__ A, const __half* __restrict__ W,
    const float* __restrict__ bq, const float* __restrict__ bk, const float* __restrict__ bv,
    __half* __restrict__ Qo, __half* __restrict__ Ko, __half* __restrict__ Vo)
{
    extern __shared__ char smem[];
    const int z = blockIdx.z;
    const __half* Wz = W + (size_t)z * DIM * DIM;
    const float* bz = (z == 0) ? bq : (z == 1) ? bk : bv;
    __half* Cz = (z == 0) ? Qo : (z == 1) ? Ko : Vo;
    gemm_body<__half>(A, Wz, bz, Cz, blockIdx.y * 128, blockIdx.x * 128, smem);
}

__global__ __launch_bounds__(256, 2) void gemm_out(
    const __half* __restrict__ A, const __half* __restrict__ W,
    const float* __restrict__ bias, float* __restrict__ C)
{
    extern __shared__ char smem[];
    gemm_body<float>(A, W, bias, C, blockIdx.y * 128, blockIdx.x * 128, smem);
}

// ---------------- fast 2^t on the FMA pipe ----------------
__device__ __forceinline__ float fexp2(float t) {
    t = fmaxf(t, -126.f);
    float z = t + 12582912.f;
    int   n = __float_as_int(z);
    float f = t - (z - 12582912.f);
    float p = 1.33335581e-3f;
    p = fmaf(p, f, 9.61812911e-3f);
    p = fmaf(p, f, 5.55041087e-2f);
    p = fmaf(p, f, 2.40226507e-1f);
    p = fmaf(p, f, 6.93147182e-1f);
    p = fmaf(p, f, 1.0f);
    return __int_as_float(__float_as_int(p) + (n << 23));
}

// ---------------- tensor-core flash attention (fp16 out) ----------------
#define ATSTR 72
#define ATILE (64 * ATSTR)
#define AQOFF 0
#define ATTN_SMEM (5 * ATILE * 2)   // 46080 B

__global__ __launch_bounds__(128) void attn_tc(
    const __half* __restrict__ Qg, const __half* __restrict__ Kg,
    const __half* __restrict__ Vg, __half* __restrict__ O)
{
    extern __shared__ char smem[];
    const uint32_t sbase = smem_to_u32(smem);
    const int tid  = threadIdx.x;
    const int lane = tid & 31;
    const int w    = tid >> 5;
    // longest-first: high qtiles (most K-tiles) scheduled first
    const int qtile = gridDim.x - 1 - blockIdx.x;
    const int h = blockIdx.y, b = blockIdx.z;
    const int q0 = qtile * 64;
    const size_t base = (size_t)b * SEQ * DIM + (size_t)h * HDIM;

    auto koff = [](int buf) { return ATILE + buf * 2 * ATILE; };
    auto voff = [](int buf) { return 2 * ATILE + buf * 2 * ATILE; };

    auto load_kv = [&](int kt, int buf) {
        const int k0 = kt * 64;
#pragma unroll
        for (int i = 0; i < 4; i++) {
            const int idx = i * 128 + tid;
            const int r = idx >> 3, c = idx & 7;
            CP_ASYNC16(sbase + (koff(buf) + r * ATSTR + c * 8) * 2,
                       Kg + base + (size_t)(k0 + r) * DIM + c * 8);
            CP_ASYNC16(sbase + (voff(buf) + r * ATSTR + c * 8) * 2,
                       Vg + base + (size_t)(k0 + r) * DIM + c * 8);
        }
    };

#pragma unroll
    for (int i = 0; i < 4; i++) {
        const int idx = i * 128 + tid;
        const int r = idx >> 3, c = idx & 7;
        CP_ASYNC16(sbase + (AQOFF + r * ATSTR + c * 8) * 2,
                   Qg + base + (size_t)(q0 + r) * DIM + c * 8);
    }
    load_kv(0, 0);
    CP_COMMIT();

    const int aRow  = lane & 15;
    const int aColB = (lane >> 4) * 16;
    const int bRow  = ((lane >> 4) & 1) * 8 + (lane & 7);
    const int bColB = ((lane >> 3) & 1) * 16;

    uint32_t qa[4][4];
    float m0 = -1e30f, m1 = -1e30f, l0 = 0.f, l1 = 0.f;
    float out[8][4];
#pragma unroll
    for (int j = 0; j < 8; j++)
#pragma unroll
        for (int f = 0; f < 4; f++) out[j][f] = 0.f;

    const float SC2 = 0.18033688011112042f;   // 0.125 * log2(e)

    for (int kt = 0; kt <= qtile; kt++) {
        const int buf = kt & 1;
        if (kt < qtile) {
            load_kv(kt + 1, buf ^ 1);
            CP_COMMIT();
            CP_WAIT(1);
        } else {
            CP_WAIT(0);
        }
        __syncthreads();

        if (kt == 0) {
#pragma unroll
            for (int c = 0; c < 4; c++)
                ldsm4(qa[c], sbase + ((AQOFF + (w * 16 + aRow) * ATSTR) * 2) + c * 32 + aColB);
        }

        const uint32_t kadr = sbase + koff(buf) * 2;
        float s[8][4];
#pragma unroll
        for (int j = 0; j < 8; j++)
#pragma unroll
            for (int f = 0; f < 4; f++) s[j][f] = 0.f;
#pragma unroll
        for (int c = 0; c < 4; c++) {
            uint32_t kb[16];
#pragma unroll
            for (int g = 0; g < 4; g++)
                ldsm4(kb + 4 * g, kadr + ((g * 16 + bRow) * ATSTR) * 2 + c * 32 + bColB);
#pragma unroll
            for (int j = 0; j < 8; j++)
                mma_f16(s[j], qa[c], kb[(j >> 1) * 4 + (j & 1) * 2],
                        kb[(j >> 1) * 4 + (j & 1) * 2 + 1]);
        }

#pragma unroll
        for (int j = 0; j < 8; j++)
#pragma unroll
            for (int f = 0; f < 4; f++) s[j][f] *= SC2;
        if (kt == qtile) {
            const int r0 = w * 16 + (lane >> 2);
            const int r1 = r0 + 8;
#pragma unroll
            for (int j = 0; j < 8; j++) {
                const int ky = j * 8 + 2 * (lane & 3);
                if (ky     > r0) s[j][0] = -1e30f;
                if (ky + 1 > r0) s[j][1] = -1e30f;
                if (ky     > r1) s[j][2] = -1e30f;
                if (ky + 1 > r1) s[j][3] = -1e30f;
            }
        }

        float mx0 = -1e30f, mx1 = -1e30f;
#pragma unroll
        for (int j = 0; j < 8; j++) {
            mx0 = fmaxf(mx0, fmaxf(s[j][0], s[j][1]));
            mx1 = fmaxf(mx1, fmaxf(s[j][2], s[j][3]));
        }
        mx0 = fmaxf(mx0, __shfl_xor_sync(0xffffffffu, mx0, 1));
        mx0 = fmaxf(mx0, __shfl_xor_sync(0xffffffffu, mx0, 2));
        mx1 = fmaxf(mx1, __shfl_xor_sync(0xffffffffu, mx1, 1));
        mx1 = fmaxf(mx1, __shfl_xor_sync(0xffffffffu, mx1, 2));
        const float nm0 = fmaxf(m0, mx0), nm1 = fmaxf(m1, mx1);
        const float cr0 = fexp2(m0 - nm0), cr1 = fexp2(m1 - nm1);
        m0 = nm0; m1 = nm1;

        float ls0 = 0.f, ls1 = 0.f;
        uint32_t pa[4][4];
#pragma unroll
        for (int c = 0; c < 4; c++) {
            const float p00 = fexp2(s[2 * c][0] - nm0);
            const float p01 = fexp2(s[2 * c][1] - nm0);
            const float p02 = fexp2(s[2 * c][2] - nm1);
            const float p03 = fexp2(s[2 * c][3] - nm1);
            const float p10 = fexp2(s[2 * c + 1][0] - nm0);
            const float p11 = fexp2(s[2 * c + 1][1] - nm0);
            const float p12 = fexp2(s[2 * c + 1][2] - nm1);
            const float p13 = fexp2(s[2 * c + 1][3] - nm1);
            ls0 += (p00 + p01) + (p10 + p11);
            ls1 += (p02 + p03) + (p12 + p13);
            pa[c][0] = packh2(p00, p01);
            pa[c][1] = packh2(p02, p03);
            pa[c][2] = packh2(p10, p11);
            pa[c][3] = packh2(p12, p13);
        }
        ls0 += __shfl_xor_sync(0xffffffffu, ls0, 1);
        ls0 += __shfl_xor_sync(0xffffffffu, ls0, 2);
        ls1 += __shfl_xor_sync(0xffffffffu, ls1, 1);
        ls1 += __shfl_xor_sync(0xffffffffu, ls1, 2);
        l0 = l0 * cr0 + ls0;
        l1 = l1 * cr1 + ls1;
#pragma unroll
        for (int j = 0; j < 8; j++) {
            out[j][0] *= cr0; out[j][1] *= cr0;
            out[j][2] *= cr1; out[j][3] *= cr1;
        }

        const uint32_t vadr = sbase + voff(buf) * 2;
#pragma unroll
        for (int c = 0; c < 4; c++) {
            uint32_t vb[16];
#pragma unroll
            for (int dg = 0; dg < 4; dg++)
                ldsm4t(vb + 4 * dg,
                       vadr + ((c * 16 + (lane & 15)) * ATSTR) * 2
                            + (dg * 16 + (lane >> 4) * 8) * 2);
#pragma unroll
            for (int j = 0; j < 8; j++)
                mma_f16(out[j], pa[c], vb[(j >> 1) * 4 + (j & 1) * 2],
                        vb[(j >> 1) * 4 + (j & 1) * 2 + 1]);
        }
        __syncthreads();
    }

    // ---- normalize + store fp16 (feeds Wo GEMM directly) ----
    const float inv0 = 1.f / l0, inv1 = 1.f / l1;
    const int r0 = q0 + w * 16 + (lane >> 2);
    __half* o0 = O + base + (size_t)r0 * DIM;
    __half* o1 = o0 + (size_t)8 * DIM;
#pragma unroll
    for (int j = 0; j < 8; j++) {
        const int cc = j * 8 + 2 * (lane & 3);
        __half2 v0 = __floats2half2_rn(out[j][0] * inv0, out[j][1] * inv0);
        __half2 v1 = __floats2half2_rn(out[j][2] * inv1, out[j][3] * inv1);
        *(__half2*)(o0 + cc) = v0;
        *(__half2*)(o1 + cc) = v1;
    }
}

// ---------------- launch ----------------
extern "C" void kernel_launch(void* const* d_in, const int* in_sizes, int n_in,
                              void* d_out, int out_size)
{
    const float* q  = (const float*)d_in[0];
    const float* Wq = (const float*)d_in[2];
    const float* bq = (const float*)d_in[3];
    const float* Wk = (const float*)d_in[4];
    const float* bk = (const float*)d_in[5];
    const float* Wv = (const float*)d_in[6];
    const float* bv = (const float*)d_in[7];
    const float* Wo = (const float*)d_in[8];
    const float* bo = (const float*)d_in[9];
    float* out = (float*)d_out;

    __half *Qh, *Kh, *Vh, *xh, *wh;
    cudaGetSymbolAddress((void**)&Qh, g_Qh);
    cudaGetSymbolAddress((void**)&Kh, g_Kh);
    cudaGetSymbolAddress((void**)&Vh, g_Vh);
    cudaGetSymbolAddress((void**)&xh, g_xh);
    cudaGetSymbolAddress((void**)&wh, g_wh);

    cudaFuncSetAttribute(gemm_qkv, cudaFuncAttributeMaxDynamicSharedMemorySize, GEMM_SMEM);
    cudaFuncSetAttribute(gemm_out, cudaFuncAttributeMaxDynamicSharedMemorySize, GEMM_SMEM);
    cudaFuncSetAttribute(attn_tc, cudaFuncAttributeMaxDynamicSharedMemorySize, ATTN_SMEM);

    const int nX4 = MROWS * DIM / 4;   // 2097152
    const int nW4 = DIM * DIM / 4;     // 262144

    // converts: activations + all 4 weights (one launch)
    cvt_kernel<<<nX4 / 256, 256>>>(q, xh, nX4);
    cvt4_kernel<<<dim3(nW4 / 256, 4), 256>>>(Wq, Wk, Wv, Wo, wh, nW4);

    // fused Q/K/V projection
    const dim3 qkvGrid(DIM / 128, MROWS / 128, 3);   // (8, 64, 3)
    gemm_qkv<<<qkvGrid, 256, GEMM_SMEM>>>(xh, wh, bq, bk, bv, Qh, Kh, Vh);

    // attention (writes fp16 into xh)
    const dim3 agrid(SEQ / 64, HEADS, BATCH);        // (32, 16, 4)
    attn_tc<<<agrid, 128, ATTN_SMEM>>>(Qh, Kh, Vh, xh);

    // output projection (fp32 out)
    const dim3 ggrid(DIM / 128, MROWS / 128);        // (8, 64)
    gemm_out<<<ggrid, 256, GEMM_SMEM>>>(xh, wh + 3 * (size_t)DIM * DIM, bo, out);
}